// round 2
// baseline (speedup 1.0000x reference)
#include <cuda_runtime.h>
#include <cuda_bf16.h>
#include <math.h>

// Problem constants (fixed by the dataset problem)
#define Bq   2
#define Nq   2048
#define Cq   1024
#define Hq   16
#define HDq  64
#define N3q  3072   // 3*C

// Scratch (device globals; no allocation allowed)
__device__ float g_q[(size_t)Bq * Hq * Nq * HDq];     // (B,H,N,hd) 16 MB
__device__ float g_att[(size_t)Bq * Nq * Cq];         // (B,N,C)    16 MB

// ---------------------------------------------------------------------------
// GEMM 1: qkv = x @ w_qkv^T   (M=4096, N=3072, K=1024)
// Epilogue scatters q -> g_q, k/v -> present region of d_out.
// 128x128 tile, BK=8, 256 threads, 8x8 per-thread microtile.
// ---------------------------------------------------------------------------
__global__ __launch_bounds__(256) void gemm_qkv_kernel(
    const float* __restrict__ X,      // (4096, 1024)
    const float* __restrict__ W,      // (3072, 1024)
    float* __restrict__ present)      // (2, B, H, N, hd)
{
    __shared__ float a_sm[8][132];
    __shared__ float b_sm[8][132];

    const int tid = threadIdx.x;
    const int tx = tid & 15;
    const int ty = tid >> 4;
    const int m0 = blockIdx.y * 128;
    const int n0 = blockIdx.x * 128;

    const int lrow = tid >> 1;
    const int lcol = (tid & 1) * 4;

    const float* Aptr = X + (size_t)(m0 + lrow) * Cq + lcol;
    const float* Bptr = W + (size_t)(n0 + lrow) * Cq + lcol;

    float acc[8][8];
    #pragma unroll
    for (int i = 0; i < 8; i++)
        #pragma unroll
        for (int j = 0; j < 8; j++) acc[i][j] = 0.f;

    for (int kk = 0; kk < Cq; kk += 8) {
        float4 av = *(const float4*)(Aptr + kk);
        float4 bv = *(const float4*)(Bptr + kk);
        __syncthreads();
        a_sm[lcol + 0][lrow] = av.x; a_sm[lcol + 1][lrow] = av.y;
        a_sm[lcol + 2][lrow] = av.z; a_sm[lcol + 3][lrow] = av.w;
        b_sm[lcol + 0][lrow] = bv.x; b_sm[lcol + 1][lrow] = bv.y;
        b_sm[lcol + 2][lrow] = bv.z; b_sm[lcol + 3][lrow] = bv.w;
        __syncthreads();

        #pragma unroll
        for (int k = 0; k < 8; k++) {
            float4 a0 = *(const float4*)&a_sm[k][ty * 8];
            float4 a1 = *(const float4*)&a_sm[k][ty * 8 + 4];
            float4 b0 = *(const float4*)&b_sm[k][tx * 8];
            float4 b1 = *(const float4*)&b_sm[k][tx * 8 + 4];
            float a[8] = {a0.x,a0.y,a0.z,a0.w,a1.x,a1.y,a1.z,a1.w};
            float b[8] = {b0.x,b0.y,b0.z,b0.w,b1.x,b1.y,b1.z,b1.w};
            #pragma unroll
            for (int i = 0; i < 8; i++)
                #pragma unroll
                for (int j = 0; j < 8; j++)
                    acc[i][j] = fmaf(a[i], b[j], acc[i][j]);
        }
    }

    // Epilogue: scatter to q / present
    #pragma unroll
    for (int i = 0; i < 8; i++) {
        const int m = m0 + ty * 8 + i;
        const int b = m >> 11;          // m / 2048
        const int n = m & 2047;
        #pragma unroll
        for (int j = 0; j < 8; j++) {
            const int col = n0 + tx * 8 + j;
            const int three = col >> 10;
            const int h = (col >> 6) & 15;
            const int d = col & 63;
            const float v = acc[i][j];
            if (three == 0) {
                g_q[(((size_t)b * Hq + h) * Nq + n) * HDq + d] = v;
            } else {
                present[((((size_t)(three - 1) * Bq + b) * Hq + h) * Nq + n) * HDq + d] = v;
            }
        }
    }
}

// ---------------------------------------------------------------------------
// Flash attention: grid (N/128, H, B), 128 threads, 1 thread = 1 query row.
// Online softmax. Causal + padding mask per element.
// Writes (B, N, C) layout scratch for the proj GEMM.
// ---------------------------------------------------------------------------
__global__ __launch_bounds__(128) void attn_kernel(
    const float* __restrict__ kv,               // present base: (2,B,H,N,hd)
    const int* __restrict__ pad,                // (B, N) int32 (bool upcast)
    const int* __restrict__ cs_ptr,
    float* __restrict__ att)                    // (B, N, C)
{
    const int b = blockIdx.z;
    const int h = blockIdx.y;
    const int q0 = blockIdx.x * 128;
    const int r = threadIdx.x;
    const int qi = q0 + r;

    __shared__ float4 k4[32 * 16];
    __shared__ float4 v4[32 * 16];
    __shared__ int padsm[32];

    const float* Qrow = g_q + (((size_t)b * Hq + h) * Nq + qi) * HDq;
    const float* Kb = kv + (((size_t)0 * Bq + b) * Hq + h) * (size_t)Nq * HDq;
    const float* Vb = kv + (((size_t)1 * Bq + b) * Hq + h) * (size_t)Nq * HDq;

    float4 q[16];
    #pragma unroll
    for (int t = 0; t < 16; t++) q[t] = ((const float4*)Qrow)[t];

    float acc[64];
    #pragma unroll
    for (int d = 0; d < 64; d++) acc[d] = 0.f;

    float m_run = -1e30f, l_run = 0.f;
    const int cs = *cs_ptr;
    const float scale = 0.125f;  // 64^-0.5

    int hi = q0 + 128;
    if (cs > hi) hi = cs;
    if (hi > Nq) hi = Nq;
    hi = (hi + 31) & ~31;

    for (int j0 = 0; j0 < hi; j0 += 32) {
        __syncthreads();
        const float4* K4g = (const float4*)(Kb + (size_t)j0 * HDq);
        const float4* V4g = (const float4*)(Vb + (size_t)j0 * HDq);
        #pragma unroll
        for (int i = 0; i < 4; i++) {
            const int f = r + 128 * i;
            k4[f] = K4g[f];
            v4[f] = V4g[f];
        }
        if (r < 32) padsm[r] = pad[(size_t)b * Nq + j0 + r];
        __syncthreads();

        float s[32];
        float tmax = -1e30f;
        #pragma unroll
        for (int j = 0; j < 32; j++) {
            const int kj = j0 + j;
            const bool ok = ((kj <= qi) || (kj < cs)) && (padsm[j] == 0);
            float d0 = 0.f, d1 = 0.f, d2 = 0.f, d3 = 0.f;
            #pragma unroll
            for (int t = 0; t < 16; t++) {
                float4 kvv = k4[j * 16 + t];
                float4 qv = q[t];
                d0 = fmaf(kvv.x, qv.x, d0);
                d1 = fmaf(kvv.y, qv.y, d1);
                d2 = fmaf(kvv.z, qv.z, d2);
                d3 = fmaf(kvv.w, qv.w, d3);
            }
            const float dot = (d0 + d1) + (d2 + d3);
            s[j] = ok ? dot * scale : -1e30f;
            tmax = fmaxf(tmax, s[j]);
        }

        const float m_new = fmaxf(m_run, tmax);
        const float corr = __expf(m_run - m_new);
        m_run = m_new;
        l_run *= corr;
        #pragma unroll
        for (int d = 0; d < 64; d++) acc[d] *= corr;

        #pragma unroll
        for (int j = 0; j < 32; j++) {
            const float p = __expf(s[j] - m_new);
            l_run += p;
            #pragma unroll
            for (int t = 0; t < 16; t++) {
                float4 vv = v4[j * 16 + t];
                acc[t * 4 + 0] = fmaf(p, vv.x, acc[t * 4 + 0]);
                acc[t * 4 + 1] = fmaf(p, vv.y, acc[t * 4 + 1]);
                acc[t * 4 + 2] = fmaf(p, vv.z, acc[t * 4 + 2]);
                acc[t * 4 + 3] = fmaf(p, vv.w, acc[t * 4 + 3]);
            }
        }
    }

    const float inv = 1.f / l_run;
    float* outp = att + ((size_t)b * Nq + qi) * Cq + h * HDq;
    #pragma unroll
    for (int t = 0; t < 16; t++) {
        float4 o;
        o.x = acc[t * 4 + 0] * inv;
        o.y = acc[t * 4 + 1] * inv;
        o.z = acc[t * 4 + 2] * inv;
        o.w = acc[t * 4 + 3] * inv;
        ((float4*)outp)[t] = o;
    }
}

// ---------------------------------------------------------------------------
// GEMM 2: out = att @ w_proj^T + b_proj  (M=4096, N=1024, K=1024)
// ---------------------------------------------------------------------------
__global__ __launch_bounds__(256) void gemm_proj_kernel(
    const float* __restrict__ X,      // (4096, 1024) = g_att
    const float* __restrict__ W,      // (1024, 1024)
    const float* __restrict__ bias,   // (1024,)
    float* __restrict__ out)          // (4096, 1024)
{
    __shared__ float a_sm[8][132];
    __shared__ float b_sm[8][132];

    const int tid = threadIdx.x;
    const int tx = tid & 15;
    const int ty = tid >> 4;
    const int m0 = blockIdx.y * 128;
    const int n0 = blockIdx.x * 128;

    const int lrow = tid >> 1;
    const int lcol = (tid & 1) * 4;

    const float* Aptr = X + (size_t)(m0 + lrow) * Cq + lcol;
    const float* Bptr = W + (size_t)(n0 + lrow) * Cq + lcol;

    float acc[8][8];
    #pragma unroll
    for (int i = 0; i < 8; i++)
        #pragma unroll
        for (int j = 0; j < 8; j++) acc[i][j] = 0.f;

    for (int kk = 0; kk < Cq; kk += 8) {
        float4 av = *(const float4*)(Aptr + kk);
        float4 bv = *(const float4*)(Bptr + kk);
        __syncthreads();
        a_sm[lcol + 0][lrow] = av.x; a_sm[lcol + 1][lrow] = av.y;
        a_sm[lcol + 2][lrow] = av.z; a_sm[lcol + 3][lrow] = av.w;
        b_sm[lcol + 0][lrow] = bv.x; b_sm[lcol + 1][lrow] = bv.y;
        b_sm[lcol + 2][lrow] = bv.z; b_sm[lcol + 3][lrow] = bv.w;
        __syncthreads();

        #pragma unroll
        for (int k = 0; k < 8; k++) {
            float4 a0 = *(const float4*)&a_sm[k][ty * 8];
            float4 a1 = *(const float4*)&a_sm[k][ty * 8 + 4];
            float4 b0 = *(const float4*)&b_sm[k][tx * 8];
            float4 b1 = *(const float4*)&b_sm[k][tx * 8 + 4];
            float a[8] = {a0.x,a0.y,a0.z,a0.w,a1.x,a1.y,a1.z,a1.w};
            float b[8] = {b0.x,b0.y,b0.z,b0.w,b1.x,b1.y,b1.z,b1.w};
            #pragma unroll
            for (int i = 0; i < 8; i++)
                #pragma unroll
                for (int j = 0; j < 8; j++)
                    acc[i][j] = fmaf(a[i], b[j], acc[i][j]);
        }
    }

    #pragma unroll
    for (int i = 0; i < 8; i++) {
        const int m = m0 + ty * 8 + i;
        #pragma unroll
        for (int j = 0; j < 8; j++) {
            const int col = n0 + tx * 8 + j;
            out[(size_t)m * Cq + col] = acc[i][j] + __ldg(&bias[col]);
        }
    }
}

// ---------------------------------------------------------------------------
// Launch
// ---------------------------------------------------------------------------
extern "C" void kernel_launch(void* const* d_in, const int* in_sizes, int n_in,
                              void* d_out, int out_size) {
    const float* x = (const float*)d_in[0];
    const int* pad = (const int*)d_in[1];
    const int* cs = (const int*)d_in[2];
    const float* w_qkv = (const float*)d_in[3];
    const float* w_proj = (const float*)d_in[4];
    const float* b_proj = (const float*)d_in[5];

    float* out = (float*)d_out;                                   // (B,N,C)
    float* present = out + (size_t)Bq * Nq * Cq;                  // (2,B,H,N,hd)

    float* attscr; cudaGetSymbolAddress((void**)&attscr, g_att);

    // 1) QKV GEMM
    {
        dim3 grid(N3q / 128, (Bq * Nq) / 128);
        gemm_qkv_kernel<<<grid, 256>>>(x, w_qkv, present);
    }
    // 2) Attention
    {
        dim3 grid(Nq / 128, Hq, Bq);
        attn_kernel<<<grid, 128>>>(present, pad, cs, attscr);
    }
    // 3) Proj GEMM + bias
    {
        dim3 grid(Cq / 128, (Bq * Nq) / 128);
        gemm_proj_kernel<<<grid, 256>>>(attscr, w_proj, b_proj, out);
    }
}

// round 7
// speedup vs baseline: 4.9235x; 4.9235x over previous
#include <cuda_runtime.h>
#include <cuda_fp16.h>
#include <mma.h>
#include <cuda_pipeline.h>
#include <math.h>

using namespace nvcuda;

#define Bq   2
#define Nq   2048
#define Cq   1024
#define Hq   16
#define HDq  64
#define N3q  3072

// ---------------- scratch ----------------
__device__ __half g_xh[(size_t)Bq * Nq * Cq];
__device__ __half g_wqkvh[(size_t)N3q * Cq];
__device__ __half g_wprojh[(size_t)Cq * Cq];
__device__ __half g_qh[(size_t)Bq * Hq * Nq * HDq];
__device__ __half g_kh[(size_t)Bq * Hq * Nq * HDq];
__device__ __half g_vh[(size_t)Bq * Hq * Nq * HDq];
__device__ __half g_atth[(size_t)Bq * Nq * Cq];

// ---------------- fp32 -> fp16 ----------------
__global__ __launch_bounds__(256) void cvt_kernel(const float* __restrict__ in,
                                                  __half* __restrict__ out, int n4) {
    int i = blockIdx.x * blockDim.x + threadIdx.x;
    if (i < n4) {
        float4 v = ((const float4*)in)[i];
        ((__half2*)out)[2 * i]     = __floats2half2_rn(v.x, v.y);
        ((__half2*)out)[2 * i + 1] = __floats2half2_rn(v.z, v.w);
    }
}

// ---------------- wmma GEMM: qkv ----------------
__global__ __launch_bounds__(256) void gemm_qkv_w(
    const __half* __restrict__ A, const __half* __restrict__ W,
    float* __restrict__ present)
{
    __shared__ __align__(16) __half Asm[2][128 * 40];
    __shared__ __align__(16) __half Bsm[2][128 * 40];

    const int tid  = threadIdx.x;
    const int lane = tid & 31;
    const int w    = tid >> 5;
    const int wm   = w >> 1;
    const int wn   = w & 1;
    const int m0   = blockIdx.y * 128;
    const int n0   = blockIdx.x * 128;
    const int srow = tid >> 2;
    const int sq   = tid & 3;

    wmma::fragment<wmma::accumulator, 16, 16, 16, float> acc[2][4];
    #pragma unroll
    for (int mt = 0; mt < 2; mt++) {
        #pragma unroll
        for (int nt = 0; nt < 4; nt++) {
            wmma::fill_fragment(acc[mt][nt], 0.0f);
        }
    }

    const int steps = Cq / 32;

    {
        __pipeline_memcpy_async(&Asm[0][srow * 40 + sq * 8],
                                A + (size_t)(m0 + srow) * Cq + sq * 8, 16);
        __pipeline_memcpy_async(&Asm[0][(srow + 64) * 40 + sq * 8],
                                A + (size_t)(m0 + srow + 64) * Cq + sq * 8, 16);
        __pipeline_memcpy_async(&Bsm[0][srow * 40 + sq * 8],
                                W + (size_t)(n0 + srow) * Cq + sq * 8, 16);
        __pipeline_memcpy_async(&Bsm[0][(srow + 64) * 40 + sq * 8],
                                W + (size_t)(n0 + srow + 64) * Cq + sq * 8, 16);
        __pipeline_commit();
    }

    for (int it = 0; it < steps; it++) {
        if (it + 1 < steps) {
            const int st = (it + 1) & 1;
            const int kk = (it + 1) * 32;
            __pipeline_memcpy_async(&Asm[st][srow * 40 + sq * 8],
                                    A + (size_t)(m0 + srow) * Cq + kk + sq * 8, 16);
            __pipeline_memcpy_async(&Asm[st][(srow + 64) * 40 + sq * 8],
                                    A + (size_t)(m0 + srow + 64) * Cq + kk + sq * 8, 16);
            __pipeline_memcpy_async(&Bsm[st][srow * 40 + sq * 8],
                                    W + (size_t)(n0 + srow) * Cq + kk + sq * 8, 16);
            __pipeline_memcpy_async(&Bsm[st][(srow + 64) * 40 + sq * 8],
                                    W + (size_t)(n0 + srow + 64) * Cq + kk + sq * 8, 16);
            __pipeline_commit();
            __pipeline_wait_prior(1);
        } else {
            __pipeline_wait_prior(0);
        }
        __syncthreads();

        const int buf = it & 1;
        #pragma unroll
        for (int ks = 0; ks < 2; ks++) {
            wmma::fragment<wmma::matrix_a, 16, 16, 16, __half, wmma::row_major> af[2];
            wmma::fragment<wmma::matrix_b, 16, 16, 16, __half, wmma::col_major> bf[4];
            #pragma unroll
            for (int mt = 0; mt < 2; mt++) {
                wmma::load_matrix_sync(af[mt],
                    &Asm[buf][(wm * 32 + mt * 16) * 40 + ks * 16], 40);
            }
            #pragma unroll
            for (int nt = 0; nt < 4; nt++) {
                wmma::load_matrix_sync(bf[nt],
                    &Bsm[buf][(wn * 64 + nt * 16) * 40 + ks * 16], 40);
            }
            #pragma unroll
            for (int mt = 0; mt < 2; mt++) {
                #pragma unroll
                for (int nt = 0; nt < 4; nt++) {
                    wmma::mma_sync(acc[mt][nt], af[mt], bf[nt], acc[mt][nt]);
                }
            }
        }
        __syncthreads();
    }

    float* stage = (float*)&Asm[0][0];
    float* ws = stage + w * (16 * 20);
    const int er = lane >> 1;
    const int ec = (lane & 1) * 8;

    #pragma unroll
    for (int mt = 0; mt < 2; mt++) {
        #pragma unroll
        for (int nt = 0; nt < 4; nt++) {
            wmma::store_matrix_sync(ws, acc[mt][nt], 20, wmma::mem_row_major);
            __syncwarp();
            const int grow = m0 + wm * 32 + mt * 16 + er;
            const int b  = grow >> 11;
            const int nn = grow & 2047;
            #pragma unroll
            for (int p = 0; p < 4; p++) {
                const int gcol = n0 + wn * 64 + nt * 16 + ec + 2 * p;
                const float v0 = ws[er * 20 + ec + 2 * p];
                const float v1 = ws[er * 20 + ec + 2 * p + 1];
                const int three = gcol >> 10;
                const int hh = (gcol >> 6) & 15;
                const int d  = gcol & 63;
                const size_t hidx = (((size_t)b * Hq + hh) * Nq + nn) * HDq + d;
                if (three == 0) {
                    *(__half2*)&g_qh[hidx] = __floats2half2_rn(v0, v1);
                } else {
                    const size_t pidx =
                        ((((size_t)(three - 1) * Bq + b) * Hq + hh) * Nq + nn) * HDq + d;
                    float2 pv; pv.x = v0; pv.y = v1;
                    *(float2*)&present[pidx] = pv;
                    if (three == 1) {
                        *(__half2*)&g_kh[hidx] = __floats2half2_rn(v0, v1);
                    } else {
                        *(__half2*)&g_vh[hidx] = __floats2half2_rn(v0, v1);
                    }
                }
            }
            __syncwarp();
        }
    }
}

// ---------------- wmma GEMM: proj ----------------
__global__ __launch_bounds__(256) void gemm_proj_w(
    const __half* __restrict__ A, const __half* __restrict__ W,
    const float* __restrict__ bias, float* __restrict__ outp)
{
    __shared__ __align__(16) __half Asm[2][128 * 40];
    __shared__ __align__(16) __half Bsm[2][128 * 40];

    const int tid  = threadIdx.x;
    const int lane = tid & 31;
    const int w    = tid >> 5;
    const int wm   = w >> 1;
    const int wn   = w & 1;
    const int m0   = blockIdx.y * 128;
    const int n0   = blockIdx.x * 128;
    const int srow = tid >> 2;
    const int sq   = tid & 3;

    wmma::fragment<wmma::accumulator, 16, 16, 16, float> acc[2][4];
    #pragma unroll
    for (int mt = 0; mt < 2; mt++) {
        #pragma unroll
        for (int nt = 0; nt < 4; nt++) {
            wmma::fill_fragment(acc[mt][nt], 0.0f);
        }
    }

    const int steps = Cq / 32;
    {
        __pipeline_memcpy_async(&Asm[0][srow * 40 + sq * 8],
                                A + (size_t)(m0 + srow) * Cq + sq * 8, 16);
        __pipeline_memcpy_async(&Asm[0][(srow + 64) * 40 + sq * 8],
                                A + (size_t)(m0 + srow + 64) * Cq + sq * 8, 16);
        __pipeline_memcpy_async(&Bsm[0][srow * 40 + sq * 8],
                                W + (size_t)(n0 + srow) * Cq + sq * 8, 16);
        __pipeline_memcpy_async(&Bsm[0][(srow + 64) * 40 + sq * 8],
                                W + (size_t)(n0 + srow + 64) * Cq + sq * 8, 16);
        __pipeline_commit();
    }

    for (int it = 0; it < steps; it++) {
        if (it + 1 < steps) {
            const int st = (it + 1) & 1;
            const int kk = (it + 1) * 32;
            __pipeline_memcpy_async(&Asm[st][srow * 40 + sq * 8],
                                    A + (size_t)(m0 + srow) * Cq + kk + sq * 8, 16);
            __pipeline_memcpy_async(&Asm[st][(srow + 64) * 40 + sq * 8],
                                    A + (size_t)(m0 + srow + 64) * Cq + kk + sq * 8, 16);
            __pipeline_memcpy_async(&Bsm[st][srow * 40 + sq * 8],
                                    W + (size_t)(n0 + srow) * Cq + kk + sq * 8, 16);
            __pipeline_memcpy_async(&Bsm[st][(srow + 64) * 40 + sq * 8],
                                    W + (size_t)(n0 + srow + 64) * Cq + kk + sq * 8, 16);
            __pipeline_commit();
            __pipeline_wait_prior(1);
        } else {
            __pipeline_wait_prior(0);
        }
        __syncthreads();

        const int buf = it & 1;
        #pragma unroll
        for (int ks = 0; ks < 2; ks++) {
            wmma::fragment<wmma::matrix_a, 16, 16, 16, __half, wmma::row_major> af[2];
            wmma::fragment<wmma::matrix_b, 16, 16, 16, __half, wmma::col_major> bf[4];
            #pragma unroll
            for (int mt = 0; mt < 2; mt++) {
                wmma::load_matrix_sync(af[mt],
                    &Asm[buf][(wm * 32 + mt * 16) * 40 + ks * 16], 40);
            }
            #pragma unroll
            for (int nt = 0; nt < 4; nt++) {
                wmma::load_matrix_sync(bf[nt],
                    &Bsm[buf][(wn * 64 + nt * 16) * 40 + ks * 16], 40);
            }
            #pragma unroll
            for (int mt = 0; mt < 2; mt++) {
                #pragma unroll
                for (int nt = 0; nt < 4; nt++) {
                    wmma::mma_sync(acc[mt][nt], af[mt], bf[nt], acc[mt][nt]);
                }
            }
        }
        __syncthreads();
    }

    float* stage = (float*)&Asm[0][0];
    float* ws = stage + w * (16 * 20);
    const int er = lane >> 1;
    const int ec = (lane & 1) * 8;

    #pragma unroll
    for (int mt = 0; mt < 2; mt++) {
        #pragma unroll
        for (int nt = 0; nt < 4; nt++) {
            wmma::store_matrix_sync(ws, acc[mt][nt], 20, wmma::mem_row_major);
            __syncwarp();
            const int grow = m0 + wm * 32 + mt * 16 + er;
            #pragma unroll
            for (int p = 0; p < 4; p++) {
                const int gcol = n0 + wn * 64 + nt * 16 + ec + 2 * p;
                float2 o;
                o.x = ws[er * 20 + ec + 2 * p]     + __ldg(&bias[gcol]);
                o.y = ws[er * 20 + ec + 2 * p + 1] + __ldg(&bias[gcol + 1]);
                *(float2*)&outp[(size_t)grow * Cq + gcol] = o;
            }
            __syncwarp();
        }
    }
}

// ---------------- wmma flash attention ----------------
__global__ __launch_bounds__(128) void attn_w(
    const int* __restrict__ pad, const int* __restrict__ cs_ptr)
{
    __shared__ __align__(16) __half qsm[64][72];
    __shared__ __align__(16) __half ksm[64][72];
    __shared__ __align__(16) __half vsm[64][72];
    __shared__ __align__(16) float sst[4][16 * 68];
    __shared__ float padf[64];

    const int b  = blockIdx.z;
    const int h  = blockIdx.y;
    const int q0 = blockIdx.x * 64;
    const int tid  = threadIdx.x;
    const int lane = tid & 31;
    const int w    = tid >> 5;
    const int cs   = *cs_ptr;

    const __half* Qg = g_qh + (((size_t)b * Hq + h) * Nq) * HDq;
    const __half* Kg = g_kh + (((size_t)b * Hq + h) * Nq) * HDq;
    const __half* Vg = g_vh + (((size_t)b * Hq + h) * Nq) * HDq;

    // stage Q: 64 rows x 64 halves = 512 x 16B chunks
    #pragma unroll
    for (int i = 0; i < 4; i++) {
        const int c = tid + 128 * i;
        const int row = c >> 3;
        const int cq = c & 7;
        *(uint4*)&qsm[row][cq * 8] = *(const uint4*)&Qg[(size_t)(q0 + row) * HDq + cq * 8];
    }
    __syncthreads();

    wmma::fragment<wmma::matrix_a, 16, 16, 16, __half, wmma::row_major> aQ[4];
    #pragma unroll
    for (int ks = 0; ks < 4; ks++) {
        wmma::load_matrix_sync(aQ[ks], &qsm[w * 16][ks * 16], 72);
    }

    const int myrow = (lane >> 1);
    const int qi = q0 + w * 16 + myrow;
    const int cb = (lane & 1) * 32;
    const float scale = 0.125f;

    float o[32];
    #pragma unroll
    for (int c = 0; c < 32; c++) o[c] = 0.f;
    float m_run = -1e30f;
    float l_run = 0.f;

    int hi = q0 + 64;
    if (cs > hi) hi = (cs < Nq) ? cs : Nq;
    const int nkb = (hi + 63) >> 6;

    for (int kbi = 0; kbi < nkb; kbi++) {
        const int kb = kbi * 64;
        __syncthreads();
        #pragma unroll
        for (int i = 0; i < 4; i++) {
            const int c = tid + 128 * i;
            const int row = c >> 3;
            const int cq = c & 7;
            *(uint4*)&ksm[row][cq * 8] = *(const uint4*)&Kg[(size_t)(kb + row) * HDq + cq * 8];
            *(uint4*)&vsm[row][cq * 8] = *(const uint4*)&Vg[(size_t)(kb + row) * HDq + cq * 8];
        }
        if (tid < 64) {
            padf[tid] = __ldg(&pad[(size_t)b * Nq + kb + tid]) ? -1e30f : 0.f;
        }
        __syncthreads();

        // S = Q @ K^T staged to sst[w]
        #pragma unroll
        for (int nt = 0; nt < 4; nt++) {
            wmma::fragment<wmma::accumulator, 16, 16, 16, float> sacc;
            wmma::fill_fragment(sacc, 0.0f);
            #pragma unroll
            for (int ks = 0; ks < 4; ks++) {
                wmma::fragment<wmma::matrix_b, 16, 16, 16, __half, wmma::col_major> bK;
                wmma::load_matrix_sync(bK, &ksm[nt * 16][ks * 16], 72);
                wmma::mma_sync(sacc, aQ[ks], bK, sacc);
            }
            wmma::store_matrix_sync(&sst[w][nt * 16], sacc, 68, wmma::mem_row_major);
        }
        __syncwarp();

        // mask + online softmax (lane pair per row)
        float s_regs[32];
        float vm = -1e30f;
        #pragma unroll
        for (int c = 0; c < 32; c++) {
            const int kcol = kb + cb + c;
            const float sval = sst[w][myrow * 68 + cb + c];
            const bool okc = (kcol <= qi) || (kcol < cs);
            s_regs[c] = okc ? (sval * scale + padf[cb + c]) : -1e30f;
            vm = fmaxf(vm, s_regs[c]);
        }
        vm = fmaxf(vm, __shfl_xor_sync(0xffffffffu, vm, 1));

        const float mn = fmaxf(m_run, vm);
        const float corr = __expf(m_run - mn);
        m_run = mn;

        float psum = 0.f;
        #pragma unroll
        for (int c = 0; c < 32; c++) {
            const float p = __expf(s_regs[c] - mn);
            s_regs[c] = p;
            psum += p;
        }
        psum += __shfl_xor_sync(0xffffffffu, psum, 1);
        l_run = l_run * corr + psum;

        __syncwarp();
        __half* pst = (__half*)&sst[w][0];
        #pragma unroll
        for (int c = 0; c < 16; c++) {
            *(__half2*)&pst[myrow * 72 + cb + 2 * c] =
                __floats2half2_rn(s_regs[2 * c], s_regs[2 * c + 1]);
        }
        __syncwarp();

        wmma::fragment<wmma::matrix_a, 16, 16, 16, __half, wmma::row_major> aP[4];
        #pragma unroll
        for (int ks = 0; ks < 4; ks++) {
            wmma::load_matrix_sync(aP[ks], pst + ks * 16, 72);
        }

        // PV staged back to sst[w]
        #pragma unroll
        for (int nt = 0; nt < 4; nt++) {
            wmma::fragment<wmma::accumulator, 16, 16, 16, float> oacc;
            wmma::fill_fragment(oacc, 0.0f);
            #pragma unroll
            for (int ks = 0; ks < 4; ks++) {
                wmma::fragment<wmma::matrix_b, 16, 16, 16, __half, wmma::row_major> bV;
                wmma::load_matrix_sync(bV, &vsm[ks * 16][nt * 16], 72);
                wmma::mma_sync(oacc, aP[ks], bV, oacc);
            }
            wmma::store_matrix_sync(&sst[w][nt * 16], oacc, 68, wmma::mem_row_major);
        }
        __syncwarp();

        #pragma unroll
        for (int c = 0; c < 32; c++) {
            o[c] = o[c] * corr + sst[w][myrow * 68 + cb + c];
        }
        __syncwarp();
    }

    const float inv = 1.f / l_run;
    __half* outp = g_atth + ((size_t)b * Nq + qi) * Cq + h * HDq + cb;
    #pragma unroll
    for (int c = 0; c < 16; c++) {
        *(__half2*)&outp[2 * c] = __floats2half2_rn(o[2 * c] * inv, o[2 * c + 1] * inv);
    }
}

// ---------------- launch ----------------
extern "C" void kernel_launch(void* const* d_in, const int* in_sizes, int n_in,
                              void* d_out, int out_size) {
    const float* x      = (const float*)d_in[0];
    const int*   pad    = (const int*)d_in[1];
    const int*   cs     = (const int*)d_in[2];
    const float* w_qkv  = (const float*)d_in[3];
    const float* w_proj = (const float*)d_in[4];
    const float* b_proj = (const float*)d_in[5];

    float* out     = (float*)d_out;
    float* present = out + (size_t)Bq * Nq * Cq;

    __half* xh;     cudaGetSymbolAddress((void**)&xh, g_xh);
    __half* wqkvh;  cudaGetSymbolAddress((void**)&wqkvh, g_wqkvh);
    __half* wprojh; cudaGetSymbolAddress((void**)&wprojh, g_wprojh);
    __half* atth;   cudaGetSymbolAddress((void**)&atth, g_atth);

    {
        int n4 = (Bq * Nq * Cq) / 4;
        cvt_kernel<<<(n4 + 255) / 256, 256>>>(x, xh, n4);
    }
    {
        int n4 = (N3q * Cq) / 4;
        cvt_kernel<<<(n4 + 255) / 256, 256>>>(w_qkv, wqkvh, n4);
    }
    {
        int n4 = (Cq * Cq) / 4;
        cvt_kernel<<<(n4 + 255) / 256, 256>>>(w_proj, wprojh, n4);
    }
    {
        dim3 grid(N3q / 128, (Bq * Nq) / 128);
        gemm_qkv_w<<<grid, 256>>>(xh, wqkvh, present);
    }
    {
        dim3 grid(Nq / 64, Hq, Bq);
        attn_w<<<grid, 128>>>(pad, cs);
    }
    {
        dim3 grid(Cq / 128, (Bq * Nq) / 128);
        gemm_proj_w<<<grid, 256>>>(atth, wprojh, b_proj, out);
    }
}